// round 8
// baseline (speedup 1.0000x reference)
#include <cuda_runtime.h>

#define BB 2
#define CCH 256
#define HH 96
#define WW 96
#define HWPIX (HH*WW)          // 9216

// d_out layout (floats): logits[2*9216] | bbox[2*4*9216] | shape[2*2*9216] | loc[2*9216]
#define OUT_LOGITS 0
#define OUT_BBOX   18432
#define OUT_SHAPE  92160
#define OUT_LOC    129024

// Scratch (device globals)
__device__ __align__(256) float g_x [(size_t)BB*HWPIX*CCH];  // NHWC input feature
__device__ __align__(256) float g_t [(size_t)BB*HWPIX*CCH];  // NHWC relu(conv3x3)
__device__ __align__(256) float g_Wc[9*256*256];             // conv_w  [tap][ic][oc]
__device__ __align__(256) float g_Wt[36*64*256];             // adapt_w [g*9+kk][c][oc]

// ---------------- f32x2 helpers (Blackwell packed fp32) ----------------
__device__ __forceinline__ unsigned long long fma2(unsigned long long a,
                                                   unsigned long long b,
                                                   unsigned long long c) {
    unsigned long long d;
    asm("fma.rn.f32x2 %0, %1, %2, %3;" : "=l"(d) : "l"(a), "l"(b), "l"(c));
    return d;
}
__device__ __forceinline__ unsigned long long pack2(float v) {
    unsigned long long d;
    asm("mov.b64 %0, {%1, %1};" : "=l"(d) : "f"(v));
    return d;
}
__device__ __forceinline__ float2 unpk(unsigned long long v) {
    float2 r;
    asm("mov.b64 {%0, %1}, %2;" : "=f"(r.x), "=f"(r.y) : "l"(v));
    return r;
}

// ------------------------------------------------------------------
// K0a: feature NCHW -> NHWC (tiled 32x32 transpose)
// grid (3, 96, 16): z = b*8 + cblk
// ------------------------------------------------------------------
__global__ void __launch_bounds__(256) k_x(const float* __restrict__ feat) {
    __shared__ float smt[32][33];
    const int bz = blockIdx.z;
    const int b  = bz >> 3;
    const int cb = bz & 7;
    const int y  = blockIdx.y;
    const int x0 = blockIdx.x * 32;
    const int lane = threadIdx.x & 31;
    const int w    = threadIdx.x >> 5;
    #pragma unroll
    for (int k = 0; k < 4; k++) {
        int ci = k * 8 + w;
        smt[ci][lane] = feat[((size_t)(b * 256 + cb * 32 + ci) * 96 + y) * 96 + x0 + lane];
    }
    __syncthreads();
    #pragma unroll
    for (int k = 0; k < 4; k++) {
        int xi = k * 8 + w;
        g_x[((size_t)(b * HWPIX) + y * 96 + x0 + xi) * 256 + cb * 32 + lane] = smt[lane][xi];
    }
}

// ------------------------------------------------------------------
// K0b: conv_w[oc][ic][tap] -> g_Wc[tap][ic][oc]
// ------------------------------------------------------------------
__global__ void __launch_bounds__(256) k_tw_conv(const float* __restrict__ conv_w) {
    int e = blockIdx.x * 256 + threadIdx.x;      // 0 .. 589823
    int oc  = e & 255;
    int r   = e >> 8;
    int ic  = r & 255;
    int tap = r >> 8;
    g_Wc[e] = conv_w[(size_t)oc * 2304 + ic * 9 + tap];
}

// ------------------------------------------------------------------
// K0c: adapt_w[oc][g*64+c][tap] -> g_Wt[g*9+kk][c][oc]
// ------------------------------------------------------------------
__global__ void __launch_bounds__(256) k_tw_adapt(const float* __restrict__ adapt_w) {
    int e = blockIdx.x * 256 + threadIdx.x;      // 0 .. 589823
    int oc   = e & 255;
    int rest = e >> 8;
    int c    = rest & 63;
    int gk   = rest >> 6;
    int g  = gk / 9;
    int kk = gk - g * 9;
    g_Wt[e] = adapt_w[(size_t)oc * 2304 + (g * 64 + c) * 9 + kk];
}

// ------------------------------------------------------------------
// K1: conv3x3 as implicit GEMM (NHWC in g_x -> NHWC g_t, bias+relu)
// block: 64 px x 256 oc, 256 threads, microtile 8px x 8oc (f32x2)
// 36 chunks = 9 taps x 4 ic-chunks of 64
// smem: s_v [64px][64c] 16KB + s_w [64c][256oc] 64KB
// ------------------------------------------------------------------
__global__ void __launch_bounds__(256, 2) k_conv(const float* __restrict__ conv_b) {
    extern __shared__ __align__(16) float sm[];
    float* s_v = sm;            // 4096
    float* s_w = sm + 4096;     // 16384

    const int tid = threadIdx.x;
    const int b   = blockIdx.y;
    const int pixBase = blockIdx.x * 64;
    const int c   = tid & 63;
    const int pb  = tid >> 6;          // 0..3
    const int pg  = tid >> 5;          // 0..7 (warp id)
    const int ocg = tid & 31;          // 0..31
    const float* xin = g_x + (size_t)b * HWPIX * 256;

    unsigned long long acc[8][4];
    #pragma unroll
    for (int i = 0; i < 8; i++)
        #pragma unroll
        for (int j = 0; j < 4; j++) acc[i][j] = 0ull;

    for (int cc = 0; cc < 36; ++cc) {
        const int tap = cc >> 2;
        const int icb = (cc & 3) << 6;
        const int ky = tap / 3 - 1;
        const int kx = tap - (tap / 3) * 3 - 1;
        __syncthreads();
        // activation tile: shifted NHWC rows, coalesced in c
        #pragma unroll
        for (int i = 0; i < 16; i++) {
            int p   = pb * 16 + i;
            int pid = pixBase + p;
            int y   = pid / 96;
            int x   = pid - y * 96;
            int yy = y + ky, xx = x + kx;
            float v = 0.f;
            if ((unsigned)yy < 96u && (unsigned)xx < 96u)
                v = xin[(size_t)((yy * 96 + xx) << 8) + icb + c];
            s_v[p * 64 + c] = v;
        }
        // weight slab [64c][256oc]
        {
            const float4* wsrc = (const float4*)(g_Wc + (size_t)cc * 16384);
            float4* wdst = (float4*)s_w;
            #pragma unroll
            for (int i = 0; i < 16; i++) wdst[tid + i * 256] = wsrc[tid + i * 256];
        }
        __syncthreads();
        // GEMM microtile
        #pragma unroll 8
        for (int cc2 = 0; cc2 < 64; ++cc2) {
            const ulonglong2* wp = (const ulonglong2*)&s_w[cc2 * 256 + ocg * 8];
            ulonglong2 wa = wp[0];
            ulonglong2 wb = wp[1];
            #pragma unroll
            for (int i = 0; i < 8; i++) {
                unsigned long long v2 = pack2(s_v[(pg * 8 + i) * 64 + cc2]);
                acc[i][0] = fma2(v2, wa.x, acc[i][0]);
                acc[i][1] = fma2(v2, wa.y, acc[i][1]);
                acc[i][2] = fma2(v2, wb.x, acc[i][2]);
                acc[i][3] = fma2(v2, wb.y, acc[i][3]);
            }
        }
    }

    float bs[8];
    #pragma unroll
    for (int j = 0; j < 8; j++) bs[j] = conv_b[ocg * 8 + j];

    #pragma unroll
    for (int i = 0; i < 8; i++) {
        int pid = pixBase + pg * 8 + i;
        float* op = &g_t[((size_t)(b * HWPIX + pid)) * 256 + ocg * 8];
        float2 u0 = unpk(acc[i][0]);
        float2 u1 = unpk(acc[i][1]);
        float2 u2 = unpk(acc[i][2]);
        float2 u3 = unpk(acc[i][3]);
        float4 o0, o1;
        o0.x = fmaxf(u0.x + bs[0], 0.f); o0.y = fmaxf(u0.y + bs[1], 0.f);
        o0.z = fmaxf(u1.x + bs[2], 0.f); o0.w = fmaxf(u1.y + bs[3], 0.f);
        o1.x = fmaxf(u2.x + bs[4], 0.f); o1.y = fmaxf(u2.y + bs[5], 0.f);
        o1.z = fmaxf(u3.x + bs[6], 0.f); o1.w = fmaxf(u3.y + bs[7], 0.f);
        ((float4*)op)[0] = o0;
        ((float4*)op)[1] = o1;
    }
}

// ------------------------------------------------------------------
// K2: per-pixel 1x1 heads on t: loc (1ch) + shape_pred (2ch)
// ------------------------------------------------------------------
__global__ void __launch_bounds__(128) k_heads1(const float* __restrict__ loc_w,
                                                const float* __restrict__ loc_b,
                                                const float* __restrict__ shape_w,
                                                const float* __restrict__ shape_b,
                                                float* __restrict__ out) {
    const int warp = threadIdx.x >> 5;
    const int lane = threadIdx.x & 31;
    const int pid  = blockIdx.x * 4 + warp;      // 0..18431

    const float4* tp  = (const float4*)&g_t[(size_t)pid * 256];
    const float4* lw  = (const float4*)loc_w;
    const float4* sw0 = (const float4*)shape_w;
    const float4* sw1 = (const float4*)(shape_w + 256);

    float sl = 0.f, s0 = 0.f, s1 = 0.f;
    #pragma unroll
    for (int q = 0; q < 2; q++) {
        float4 t  = tp[lane * 2 + q];
        float4 a  = lw[lane * 2 + q];
        float4 b0 = sw0[lane * 2 + q];
        float4 b1 = sw1[lane * 2 + q];
        sl += t.x * a.x + t.y * a.y + t.z * a.z + t.w * a.w;
        s0 += t.x * b0.x + t.y * b0.y + t.z * b0.z + t.w * b0.w;
        s1 += t.x * b1.x + t.y * b1.y + t.z * b1.z + t.w * b1.w;
    }
    #pragma unroll
    for (int off = 16; off > 0; off >>= 1) {
        sl += __shfl_xor_sync(0xffffffffu, sl, off);
        s0 += __shfl_xor_sync(0xffffffffu, s0, off);
        s1 += __shfl_xor_sync(0xffffffffu, s1, off);
    }
    if (lane == 0) {
        int b   = pid / HWPIX;
        int rem = pid - b * HWPIX;
        out[OUT_LOC   + b * HWPIX + rem]           = sl + loc_b[0];
        out[OUT_SHAPE + (b * 2 + 0) * HWPIX + rem] = s0 + shape_b[0];
        out[OUT_SHAPE + (b * 2 + 1) * HWPIX + rem] = s1 + shape_b[1];
    }
}

// ------------------------------------------------------------------
// K3: fused deformable conv + relu + cls/bbox heads
// block: 64 px x 256 oc, 256 threads, microtile 8px x 8oc (f32x2)
// 36 chunks = 4 groups x 9 kernel points, 64 c each
// smem: s_v 16KB + s_w 64KB + s_shp 512B + s_ow 576B
// ------------------------------------------------------------------
__global__ void __launch_bounds__(256, 2) k_deform(const float* __restrict__ offset_w,
                                                   const float* __restrict__ cls_w,
                                                   const float* __restrict__ cls_b,
                                                   const float* __restrict__ bbox_w,
                                                   const float* __restrict__ bbox_b,
                                                   float* __restrict__ out) {
    extern __shared__ __align__(16) float sm[];
    float* s_v   = sm;             // 4096
    float* s_w   = sm + 4096;      // 16384
    float* s_shp = sm + 20480;     // 128  [p][2]
    float* s_ow  = sm + 20608;     // 144

    const int tid = threadIdx.x;
    const int b   = blockIdx.y;
    const int pixBase = blockIdx.x * 64;
    const int c   = tid & 63;
    const int pb  = tid >> 6;
    const int pg  = tid >> 5;
    const int ocg = tid & 31;
    const float* tb = g_t + (size_t)b * HWPIX * 256;

    // preload offset coefficients and shape predictions
    if (tid < 144) s_ow[tid] = offset_w[tid];
    if (tid < 128) {
        int p = tid >> 1, comp = tid & 1;
        s_shp[tid] = out[OUT_SHAPE + (b * 2 + comp) * HWPIX + pixBase + p];
    }

    unsigned long long acc[8][4];
    #pragma unroll
    for (int i = 0; i < 8; i++)
        #pragma unroll
        for (int j = 0; j < 4; j++) acc[i][j] = 0ull;

    for (int gk = 0; gk < 36; ++gk) {
        const int g  = gk / 9;
        const int kk = gk - g * 9;
        const int ky = kk / 3 - 1;
        const int kx = kk - (kk / 3) * 3 - 1;
        __syncthreads();   // buffers free / (iter0) preload visible
        const int o = (g * 18 + kk * 2) * 2;
        const float cy0 = s_ow[o + 0], cy1 = s_ow[o + 1];
        const float cx0 = s_ow[o + 2], cx1 = s_ow[o + 3];
        const float* base = tb + (g << 6) + c;
        // bilinear gather, coalesced in c
        #pragma unroll
        for (int i = 0; i < 16; i++) {
            int p   = pb * 16 + i;
            int pid = pixBase + p;
            int y   = pid / 96;
            int x   = pid - y * 96;
            float sv0 = s_shp[p * 2], sv1 = s_shp[p * 2 + 1];
            float py = (float)(y + ky) + sv0 * cy0 + sv1 * cy1;
            float px = (float)(x + kx) + sv0 * cx0 + sv1 * cx1;
            float y0f = floorf(py), x0f = floorf(px);
            float wy = py - y0f, wx = px - x0f;
            int y0 = (int)y0f, x0 = (int)x0f;
            float w00 = (1.f - wy) * (1.f - wx);
            float w01 = (1.f - wy) * wx;
            float w10 = wy * (1.f - wx);
            float w11 = wy * wx;
            bool yv0 = (unsigned)y0       < (unsigned)HH;
            bool yv1 = (unsigned)(y0 + 1) < (unsigned)HH;
            bool xv0 = (unsigned)x0       < (unsigned)WW;
            bool xv1 = (unsigned)(x0 + 1) < (unsigned)WW;
            float v = 0.f;
            if (yv0 && xv0) v += w00 * base[(size_t)((y0 * 96 + x0)           << 8)];
            if (yv0 && xv1) v += w01 * base[(size_t)((y0 * 96 + x0 + 1)       << 8)];
            if (yv1 && xv0) v += w10 * base[(size_t)(((y0 + 1) * 96 + x0)     << 8)];
            if (yv1 && xv1) v += w11 * base[(size_t)(((y0 + 1) * 96 + x0 + 1) << 8)];
            s_v[p * 64 + c] = v;
        }
        // weight slab
        {
            const float4* wsrc = (const float4*)(g_Wt + (size_t)gk * 16384);
            float4* wdst = (float4*)s_w;
            #pragma unroll
            for (int i = 0; i < 16; i++) wdst[tid + i * 256] = wsrc[tid + i * 256];
        }
        __syncthreads();
        // GEMM microtile
        #pragma unroll 8
        for (int cc2 = 0; cc2 < 64; ++cc2) {
            const ulonglong2* wp = (const ulonglong2*)&s_w[cc2 * 256 + ocg * 8];
            ulonglong2 wa = wp[0];
            ulonglong2 wb = wp[1];
            #pragma unroll
            for (int i = 0; i < 8; i++) {
                unsigned long long v2 = pack2(s_v[(pg * 8 + i) * 64 + cc2]);
                acc[i][0] = fma2(v2, wa.x, acc[i][0]);
                acc[i][1] = fma2(v2, wa.y, acc[i][1]);
                acc[i][2] = fma2(v2, wb.x, acc[i][2]);
                acc[i][3] = fma2(v2, wb.y, acc[i][3]);
            }
        }
    }

    // fused heads: relu(ta) then cls + 4 bbox dots
    float hw[5][8];
    #pragma unroll
    for (int j = 0; j < 8; j++) {
        hw[0][j] = cls_w[ocg * 8 + j];
        hw[1][j] = bbox_w[0 * 256 + ocg * 8 + j];
        hw[2][j] = bbox_w[1 * 256 + ocg * 8 + j];
        hw[3][j] = bbox_w[2 * 256 + ocg * 8 + j];
        hw[4][j] = bbox_w[3 * 256 + ocg * 8 + j];
    }
    __syncthreads();                // last GEMM reads of s_w done
    float* s_red = s_w;             // [jj*64+p][32] = 10240 floats
    #pragma unroll
    for (int i = 0; i < 8; i++) {
        int p = pg * 8 + i;
        float2 u0 = unpk(acc[i][0]);
        float2 u1 = unpk(acc[i][1]);
        float2 u2 = unpk(acc[i][2]);
        float2 u3 = unpk(acc[i][3]);
        float r[8];
        r[0] = fmaxf(u0.x, 0.f); r[1] = fmaxf(u0.y, 0.f);
        r[2] = fmaxf(u1.x, 0.f); r[3] = fmaxf(u1.y, 0.f);
        r[4] = fmaxf(u2.x, 0.f); r[5] = fmaxf(u2.y, 0.f);
        r[6] = fmaxf(u3.x, 0.f); r[7] = fmaxf(u3.y, 0.f);
        #pragma unroll
        for (int jj = 0; jj < 5; jj++) {
            float s = 0.f;
            #pragma unroll
            for (int j = 0; j < 8; j++) s += hw[jj][j] * r[j];
            s_red[(jj * 64 + p) * 32 + ocg] = s;
        }
    }
    __syncthreads();
    for (int e = tid; e < 320; e += 256) {
        int jj = e >> 6;
        int p  = e & 63;
        float s = 0.f;
        #pragma unroll
        for (int oo = 0; oo < 32; oo++) s += s_red[(jj * 64 + p) * 32 + oo];
        int pid = pixBase + p;
        if (jj == 0)
            out[OUT_LOGITS + b * HWPIX + pid] = s + cls_b[0];
        else
            out[OUT_BBOX + (b * 4 + (jj - 1)) * HWPIX + pid] = s + bbox_b[jj - 1];
    }
}

// ------------------------------------------------------------------
extern "C" void kernel_launch(void* const* d_in, const int* in_sizes, int n_in,
                              void* d_out, int out_size) {
    (void)in_sizes; (void)n_in; (void)out_size;
    const float* feature  = (const float*)d_in[0];
    const float* conv_w   = (const float*)d_in[1];
    const float* conv_b   = (const float*)d_in[2];
    const float* loc_w    = (const float*)d_in[3];
    const float* loc_b    = (const float*)d_in[4];
    const float* shape_w  = (const float*)d_in[5];
    const float* shape_b  = (const float*)d_in[6];
    const float* offset_w = (const float*)d_in[7];
    const float* adapt_w  = (const float*)d_in[8];
    const float* cls_w    = (const float*)d_in[9];
    const float* cls_b    = (const float*)d_in[10];
    const float* bbox_w   = (const float*)d_in[11];
    const float* bbox_b   = (const float*)d_in[12];
    float* out = (float*)d_out;

    static int attr_done = 0;
    if (!attr_done) {
        cudaFuncSetAttribute(k_conv,   cudaFuncAttributeMaxDynamicSharedMemorySize, 20480 * 4);
        cudaFuncSetAttribute(k_deform, cudaFuncAttributeMaxDynamicSharedMemorySize, 20752 * 4);
        attr_done = 1;
    }

    k_x<<<dim3(3, 96, 16), 256>>>(feature);
    k_tw_conv<<<2304, 256>>>(conv_w);
    k_tw_adapt<<<2304, 256>>>(adapt_w);
    k_conv<<<dim3(144, 2), 256, 20480 * 4>>>(conv_b);
    k_heads1<<<4608, 128>>>(loc_w, loc_b, shape_w, shape_b, out);
    k_deform<<<dim3(144, 2), 256, 20752 * 4>>>(
        offset_w, cls_w, cls_b, bbox_w, bbox_b, out);
}

// round 9
// speedup vs baseline: 1.0095x; 1.0095x over previous
#include <cuda_runtime.h>

#define BB 2
#define CCH 256
#define HH 96
#define WW 96
#define HWPIX (HH*WW)          // 9216

// d_out layout (floats): logits[2*9216] | bbox[2*4*9216] | shape[2*2*9216] | loc[2*9216]
#define OUT_LOGITS 0
#define OUT_BBOX   18432
#define OUT_SHAPE  92160
#define OUT_LOC    129024

// Scratch (device globals)
__device__ __align__(256) float g_x [(size_t)BB*HWPIX*CCH];  // NHWC input feature
__device__ __align__(256) float g_t [(size_t)BB*HWPIX*CCH];  // NHWC relu(conv3x3)
__device__ __align__(256) float g_Wc[9*256*256];             // conv_w  [tap][ic][ocmap]
__device__ __align__(256) float g_Wt[36*64*256];             // adapt_w [g*9+kk][c][ocmap]

// ---------------- f32x2 helpers (Blackwell packed fp32) ----------------
__device__ __forceinline__ unsigned long long fma2(unsigned long long a,
                                                   unsigned long long b,
                                                   unsigned long long c) {
    unsigned long long d;
    asm("fma.rn.f32x2 %0, %1, %2, %3;" : "=l"(d) : "l"(a), "l"(b), "l"(c));
    return d;
}
__device__ __forceinline__ unsigned long long pack2(float v) {
    unsigned long long d;
    asm("mov.b64 %0, {%1, %1};" : "=l"(d) : "f"(v));
    return d;
}
__device__ __forceinline__ float2 unpk(unsigned long long v) {
    float2 r;
    asm("mov.b64 {%0, %1}, %2;" : "=f"(r.x), "=f"(r.y) : "l"(v));
    return r;
}

// oc remap: two 128-float planes of interleaved quads so warp LDS.128 reads are
// contiguous. plane = (oc>>2)&1, slot = (oc>>3)*4 + (oc&3).
// Thread reading quad ocg of plane0 + quad ocg of plane1 gets oc = ocg*8 .. ocg*8+7.
__device__ __forceinline__ int ocmap(int oc) {
    return (((oc >> 2) & 1) << 7) + ((oc >> 3) << 2) + (oc & 3);
}

// ------------------------------------------------------------------
// K0a: feature NCHW -> NHWC (tiled 32x32 transpose)
// ------------------------------------------------------------------
__global__ void __launch_bounds__(256) k_x(const float* __restrict__ feat) {
    __shared__ float smt[32][33];
    const int bz = blockIdx.z;
    const int b  = bz >> 3;
    const int cb = bz & 7;
    const int y  = blockIdx.y;
    const int x0 = blockIdx.x * 32;
    const int lane = threadIdx.x & 31;
    const int w    = threadIdx.x >> 5;
    #pragma unroll
    for (int k = 0; k < 4; k++) {
        int ci = k * 8 + w;
        smt[ci][lane] = feat[((size_t)(b * 256 + cb * 32 + ci) * 96 + y) * 96 + x0 + lane];
    }
    __syncthreads();
    #pragma unroll
    for (int k = 0; k < 4; k++) {
        int xi = k * 8 + w;
        g_x[((size_t)(b * HWPIX) + y * 96 + x0 + xi) * 256 + cb * 32 + lane] = smt[lane][xi];
    }
}

// ------------------------------------------------------------------
// K0b: conv_w[oc][ic][tap] -> g_Wc[tap][ic][ocmap(oc)]
// ------------------------------------------------------------------
__global__ void __launch_bounds__(256) k_tw_conv(const float* __restrict__ conv_w) {
    int e = blockIdx.x * 256 + threadIdx.x;      // 0 .. 589823
    int oc  = e & 255;
    int r   = e >> 8;
    int ic  = r & 255;
    int tap = r >> 8;
    g_Wc[((size_t)tap << 16) + (ic << 8) + ocmap(oc)] =
        conv_w[(size_t)oc * 2304 + ic * 9 + tap];
}

// ------------------------------------------------------------------
// K0c: adapt_w[oc][g*64+c][tap] -> g_Wt[g*9+kk][c][ocmap(oc)]
// ------------------------------------------------------------------
__global__ void __launch_bounds__(256) k_tw_adapt(const float* __restrict__ adapt_w) {
    int e = blockIdx.x * 256 + threadIdx.x;      // 0 .. 589823
    int oc   = e & 255;
    int rest = e >> 8;
    int c    = rest & 63;
    int gk   = rest >> 6;
    int g  = gk / 9;
    int kk = gk - g * 9;
    g_Wt[((size_t)gk << 14) + (c << 8) + ocmap(oc)] =
        adapt_w[(size_t)oc * 2304 + (g * 64 + c) * 9 + kk];
}

// ---------------- shared GEMM inner step (swizzled s_v, planar s_w) ----------
// s_v layout: [c][ p ^ (c&31) ], 64x64
// s_w layout: [c][plane0 128 | plane1 128]
#define GEMM_CHUNK(s_v, s_w, pg8, ocg, acc)                                     \
    for (int cb = 0; cb < 64; cb += 8) {                                        \
        _Pragma("unroll")                                                       \
        for (int u = 0; u < 8; ++u) {                                           \
            const int cc2 = cb + u;                                             \
            ulonglong2 wa = *(const ulonglong2*)&s_w[(cc2 << 8) + (ocg << 2)];  \
            ulonglong2 wb = *(const ulonglong2*)&s_w[(cc2 << 8) + 128 + (ocg << 2)]; \
            const int m28 = (cb & 24) | (u & 4);                                \
            const float* vrow = &s_v[cc2 << 6];                                 \
            float4 v0 = *(const float4*)&vrow[(pg8) ^ m28];                     \
            float4 v1 = *(const float4*)&vrow[(pg8 + 4) ^ m28];                 \
            const int t = u & 3;                                                \
            float va[8];                                                        \
            va[0 ^ t] = v0.x; va[1 ^ t] = v0.y;                                 \
            va[2 ^ t] = v0.z; va[3 ^ t] = v0.w;                                 \
            va[4 + (0 ^ t)] = v1.x; va[4 + (1 ^ t)] = v1.y;                     \
            va[4 + (2 ^ t)] = v1.z; va[4 + (3 ^ t)] = v1.w;                     \
            _Pragma("unroll")                                                   \
            for (int i = 0; i < 8; i++) {                                       \
                unsigned long long v2 = pack2(va[i]);                           \
                acc[i][0] = fma2(v2, wa.x, acc[i][0]);                          \
                acc[i][1] = fma2(v2, wa.y, acc[i][1]);                          \
                acc[i][2] = fma2(v2, wb.x, acc[i][2]);                          \
                acc[i][3] = fma2(v2, wb.y, acc[i][3]);                          \
            }                                                                   \
        }                                                                       \
    }

// ------------------------------------------------------------------
// K1: conv3x3 implicit GEMM + bias + relu -> g_t, fused loc/shape heads
// block: 64 px x 256 oc, 256 threads, microtile 8px x 8oc (f32x2)
// ------------------------------------------------------------------
__global__ void __launch_bounds__(256, 2) k_conv(const float* __restrict__ conv_b,
                                                 const float* __restrict__ loc_w,
                                                 const float* __restrict__ loc_b,
                                                 const float* __restrict__ shape_w,
                                                 const float* __restrict__ shape_b,
                                                 float* __restrict__ out) {
    extern __shared__ __align__(16) float sm[];
    float* s_v  = sm;                  // 4096
    float* s_w  = sm + 4096;           // 16384
    int2*  s_yx = (int2*)(sm + 20480); // 64

    const int tid = threadIdx.x;
    const int b   = blockIdx.y;
    const int pixBase = blockIdx.x * 64;
    const int c   = tid & 63;
    const int pb  = tid >> 6;          // 0..3
    const int pg  = tid >> 5;          // 0..7
    const int pg8 = pg * 8;
    const int ocg = tid & 31;
    const float* xin = g_x + (size_t)b * HWPIX * 256;

    if (tid < 64) {
        int pid = pixBase + tid;
        int y = pid / 96;
        s_yx[tid] = make_int2(y, pid - y * 96);
    }

    unsigned long long acc[8][4];
    #pragma unroll
    for (int i = 0; i < 8; i++)
        #pragma unroll
        for (int j = 0; j < 4; j++) acc[i][j] = 0ull;

    const int csw = (c & 31);
    for (int cc = 0; cc < 36; ++cc) {
        const int tap = cc >> 2;
        const int icb = (cc & 3) << 6;
        const int ky = tap / 3 - 1;
        const int kx = tap - (tap / 3) * 3 - 1;
        __syncthreads();
        // activation tile -> swizzled [c][px]
        #pragma unroll
        for (int i = 0; i < 16; i++) {
            int p = pb * 16 + i;
            int2 yx = s_yx[p];
            int yy = yx.x + ky, xx = yx.y + kx;
            float v = 0.f;
            if ((unsigned)yy < 96u && (unsigned)xx < 96u)
                v = xin[(size_t)((yy * 96 + xx) << 8) + icb + c];
            s_v[(c << 6) + (p ^ csw)] = v;
        }
        // weight slab (already planar-ocmap layout)
        {
            const float4* wsrc = (const float4*)(g_Wc + (size_t)cc * 16384);
            float4* wdst = (float4*)s_w;
            #pragma unroll
            for (int i = 0; i < 16; i++) wdst[tid + i * 256] = wsrc[tid + i * 256];
        }
        __syncthreads();
        GEMM_CHUNK(s_v, s_w, pg8, ocg, acc)
    }

    float bs[8], h0[8], h1[8], h2[8];
    #pragma unroll
    for (int j = 0; j < 8; j++) {
        bs[j] = conv_b[ocg * 8 + j];
        h0[j] = loc_w[ocg * 8 + j];
        h1[j] = shape_w[ocg * 8 + j];
        h2[j] = shape_w[256 + ocg * 8 + j];
    }
    __syncthreads();               // GEMM reads of s_w/s_v finished
    float* s_red = s_w;            // [head][64px][32] = 6144 floats
    #pragma unroll
    for (int i = 0; i < 8; i++) {
        int p = pg8 + i;
        int pid = pixBase + p;
        float2 u0 = unpk(acc[i][0]);
        float2 u1 = unpk(acc[i][1]);
        float2 u2 = unpk(acc[i][2]);
        float2 u3 = unpk(acc[i][3]);
        float r[8];
        r[0] = fmaxf(u0.x + bs[0], 0.f); r[1] = fmaxf(u0.y + bs[1], 0.f);
        r[2] = fmaxf(u1.x + bs[2], 0.f); r[3] = fmaxf(u1.y + bs[3], 0.f);
        r[4] = fmaxf(u2.x + bs[4], 0.f); r[5] = fmaxf(u2.y + bs[5], 0.f);
        r[6] = fmaxf(u3.x + bs[6], 0.f); r[7] = fmaxf(u3.y + bs[7], 0.f);
        float* op = &g_t[((size_t)(b * HWPIX + pid)) * 256 + ocg * 8];
        ((float4*)op)[0] = make_float4(r[0], r[1], r[2], r[3]);
        ((float4*)op)[1] = make_float4(r[4], r[5], r[6], r[7]);
        float sl = 0.f, s0 = 0.f, s1 = 0.f;
        #pragma unroll
        for (int j = 0; j < 8; j++) {
            sl += h0[j] * r[j];
            s0 += h1[j] * r[j];
            s1 += h2[j] * r[j];
        }
        s_red[(0 * 64 + p) * 32 + ocg] = sl;
        s_red[(1 * 64 + p) * 32 + ocg] = s0;
        s_red[(2 * 64 + p) * 32 + ocg] = s1;
    }
    __syncthreads();
    if (tid < 192) {
        int head = tid >> 6;
        int p    = tid & 63;
        float s = 0.f;
        #pragma unroll
        for (int o = 0; o < 32; o++) s += s_red[(head * 64 + p) * 32 + o];
        int pid = pixBase + p;
        if (head == 0)
            out[OUT_LOC + b * HWPIX + pid] = s + loc_b[0];
        else
            out[OUT_SHAPE + (b * 2 + head - 1) * HWPIX + pid] = s + shape_b[head - 1];
    }
}

// ------------------------------------------------------------------
// K3: fused deformable conv + relu + cls/bbox heads
// ------------------------------------------------------------------
__global__ void __launch_bounds__(256, 2) k_deform(const float* __restrict__ offset_w,
                                                   const float* __restrict__ cls_w,
                                                   const float* __restrict__ cls_b,
                                                   const float* __restrict__ bbox_w,
                                                   const float* __restrict__ bbox_b,
                                                   float* __restrict__ out) {
    extern __shared__ __align__(16) float sm[];
    float*  s_v   = sm;                    // 4096
    float*  s_w   = sm + 4096;             // 16384
    float*  s_shp = sm + 20480;            // 128  [p][2]
    float*  s_ow  = sm + 20608;            // 144
    float2* s_fyx = (float2*)(sm + 20752); // 64

    const int tid = threadIdx.x;
    const int b   = blockIdx.y;
    const int pixBase = blockIdx.x * 64;
    const int c   = tid & 63;
    const int pb  = tid >> 6;
    const int pg  = tid >> 5;
    const int pg8 = pg * 8;
    const int ocg = tid & 31;
    const float* tb = g_t + (size_t)b * HWPIX * 256;

    if (tid < 144) s_ow[tid] = offset_w[tid];
    if (tid < 128) {
        int p = tid >> 1, comp = tid & 1;
        s_shp[tid] = out[OUT_SHAPE + (b * 2 + comp) * HWPIX + pixBase + p];
    }
    if (tid >= 192) {
        int p = tid - 192;
        int pid = pixBase + p;
        int y = pid / 96;
        s_fyx[p] = make_float2((float)y, (float)(pid - y * 96));
    } else if (tid >= 128 && tid < 192) {
        // cover remaining px 0..63 split: threads 144..207 handled above/below; use simple scheme instead
    }
    // simpler: all 64 px by threads 64..127 (no overlap with other preloads)
    if (tid >= 64 && tid < 128) {
        int p = tid - 64;
        int pid = pixBase + p;
        int y = pid / 96;
        s_fyx[p] = make_float2((float)y, (float)(pid - y * 96));
    }

    unsigned long long acc[8][4];
    #pragma unroll
    for (int i = 0; i < 8; i++)
        #pragma unroll
        for (int j = 0; j < 4; j++) acc[i][j] = 0ull;

    const int csw = (c & 31);
    for (int gk = 0; gk < 36; ++gk) {
        const int g  = gk / 9;
        const int kk = gk - g * 9;
        const float fky = (float)(kk / 3 - 1);
        const float fkx = (float)(kk - (kk / 3) * 3 - 1);
        __syncthreads();   // buffers free / (iter0) preload visible
        const int o = (g * 18 + kk * 2) * 2;
        const float cy0 = s_ow[o + 0], cy1 = s_ow[o + 1];
        const float cx0 = s_ow[o + 2], cx1 = s_ow[o + 3];
        const float* base = tb + (g << 6) + c;
        // bilinear gather -> swizzled [c][px]
        #pragma unroll
        for (int i = 0; i < 16; i++) {
            int p = pb * 16 + i;
            float2 fyx = s_fyx[p];
            float sv0 = s_shp[p * 2], sv1 = s_shp[p * 2 + 1];
            float py = fyx.x + fky + sv0 * cy0 + sv1 * cy1;
            float px = fyx.y + fkx + sv0 * cx0 + sv1 * cx1;
            float y0f = floorf(py), x0f = floorf(px);
            float wy = py - y0f, wx = px - x0f;
            int y0 = (int)y0f, x0 = (int)x0f;
            float w00 = (1.f - wy) * (1.f - wx);
            float w01 = (1.f - wy) * wx;
            float w10 = wy * (1.f - wx);
            float w11 = wy * wx;
            bool yv0 = (unsigned)y0       < (unsigned)HH;
            bool yv1 = (unsigned)(y0 + 1) < (unsigned)HH;
            bool xv0 = (unsigned)x0       < (unsigned)WW;
            bool xv1 = (unsigned)(x0 + 1) < (unsigned)WW;
            float v = 0.f;
            if (yv0 && xv0) v += w00 * base[(size_t)((y0 * 96 + x0)           << 8)];
            if (yv0 && xv1) v += w01 * base[(size_t)((y0 * 96 + x0 + 1)       << 8)];
            if (yv1 && xv0) v += w10 * base[(size_t)(((y0 + 1) * 96 + x0)     << 8)];
            if (yv1 && xv1) v += w11 * base[(size_t)(((y0 + 1) * 96 + x0 + 1) << 8)];
            s_v[(c << 6) + (p ^ csw)] = v;
        }
        // weight slab
        {
            const float4* wsrc = (const float4*)(g_Wt + (size_t)gk * 16384);
            float4* wdst = (float4*)s_w;
            #pragma unroll
            for (int i = 0; i < 16; i++) wdst[tid + i * 256] = wsrc[tid + i * 256];
        }
        __syncthreads();
        GEMM_CHUNK(s_v, s_w, pg8, ocg, acc)
    }

    // fused heads: relu(ta) then cls + 4 bbox dots
    float hw[5][8];
    #pragma unroll
    for (int j = 0; j < 8; j++) {
        hw[0][j] = cls_w[ocg * 8 + j];
        hw[1][j] = bbox_w[0 * 256 + ocg * 8 + j];
        hw[2][j] = bbox_w[1 * 256 + ocg * 8 + j];
        hw[3][j] = bbox_w[2 * 256 + ocg * 8 + j];
        hw[4][j] = bbox_w[3 * 256 + ocg * 8 + j];
    }
    __syncthreads();                // last GEMM reads of s_w done
    float* s_red = s_w;             // [jj*64+p][32] = 10240 floats
    #pragma unroll
    for (int i = 0; i < 8; i++) {
        int p = pg8 + i;
        float2 u0 = unpk(acc[i][0]);
        float2 u1 = unpk(acc[i][1]);
        float2 u2 = unpk(acc[i][2]);
        float2 u3 = unpk(acc[i][3]);
        float r[8];
        r[0] = fmaxf(u0.x, 0.f); r[1] = fmaxf(u0.y, 0.f);
        r[2] = fmaxf(u1.x, 0.f); r[3] = fmaxf(u1.y, 0.f);
        r[4] = fmaxf(u2.x, 0.f); r[5] = fmaxf(u2.y, 0.f);
        r[6] = fmaxf(u3.x, 0.f); r[7] = fmaxf(u3.y, 0.f);
        #pragma unroll
        for (int jj = 0; jj < 5; jj++) {
            float s = 0.f;
            #pragma unroll
            for (int j = 0; j < 8; j++) s += hw[jj][j] * r[j];
            s_red[(jj * 64 + p) * 32 + ocg] = s;
        }
    }
    __syncthreads();
    for (int e = tid; e < 320; e += 256) {
        int jj = e >> 6;
        int p  = e & 63;
        float s = 0.f;
        #pragma unroll
        for (int oo = 0; oo < 32; oo++) s += s_red[(jj * 64 + p) * 32 + oo];
        int pid = pixBase + p;
        if (jj == 0)
            out[OUT_LOGITS + b * HWPIX + pid] = s + cls_b[0];
        else
            out[OUT_BBOX + (b * 4 + (jj - 1)) * HWPIX + pid] = s + bbox_b[jj - 1];
    }
}

// ------------------------------------------------------------------
extern "C" void kernel_launch(void* const* d_in, const int* in_sizes, int n_in,
                              void* d_out, int out_size) {
    (void)in_sizes; (void)n_in; (void)out_size;
    const float* feature  = (const float*)d_in[0];
    const float* conv_w   = (const float*)d_in[1];
    const float* conv_b   = (const float*)d_in[2];
    const float* loc_w    = (const float*)d_in[3];
    const float* loc_b    = (const float*)d_in[4];
    const float* shape_w  = (const float*)d_in[5];
    const float* shape_b  = (const float*)d_in[6];
    const float* offset_w = (const float*)d_in[7];
    const float* adapt_w  = (const float*)d_in[8];
    const float* cls_w    = (const float*)d_in[9];
    const float* cls_b    = (const float*)d_in[10];
    const float* bbox_w   = (const float*)d_in[11];
    const float* bbox_b   = (const float*)d_in[12];
    float* out = (float*)d_out;

    static int attr_done = 0;
    if (!attr_done) {
        cudaFuncSetAttribute(k_conv,   cudaFuncAttributeMaxDynamicSharedMemorySize, 20608 * 4);
        cudaFuncSetAttribute(k_deform, cudaFuncAttributeMaxDynamicSharedMemorySize, 20880 * 4);
        attr_done = 1;
    }

    k_x<<<dim3(3, 96, 16), 256>>>(feature);
    k_tw_conv<<<2304, 256>>>(conv_w);
    k_tw_adapt<<<2304, 256>>>(adapt_w);
    k_conv<<<dim3(144, 2), 256, 20608 * 4>>>(conv_b, loc_w, loc_b, shape_w, shape_b, out);
    k_deform<<<dim3(144, 2), 256, 20880 * 4>>>(
        offset_w, cls_w, cls_b, bbox_w, bbox_b, out);
}